// round 17
// baseline (speedup 1.0000x reference)
#include <cuda_runtime.h>
#include <cuda_bf16.h>
#include <cstdint>

#define BB 512
#define SS 200
#define HH 256
#define MROWS (BB * SS)        // 102400 = 1600 * 64
#define MT64 1600
#define NCH 16                 // K chunks of 16
#define UCHUNK 8192            // U chunk: hi 4KB | lo 4KB (tiled128, 128 cols x 16 k)

// ---------------- scratch (no cudaMalloc allowed) ----------------
__device__ float g_l[BB * HH];
__device__ float g_sc[2 * MROWS];            // partial scores per n-half
__device__ __align__(128) char g_Uc[2 * NCH * UCHUNK];   // 256KB

// ---------------- helpers ----------------
__device__ __forceinline__ uint32_t smem_u32(const void* p) {
    uint32_t a;
    asm("{ .reg .u64 t; cvta.to.shared.u64 t, %1; cvt.u32.u64 %0, t; }" : "=r"(a) : "l"(p));
    return a;
}
__device__ __forceinline__ uint32_t pack_bf2(float x, float y) {
    uint32_t a = (uint32_t)__bfloat16_as_ushort(__float2bfloat16_rn(x));
    uint32_t b = (uint32_t)__bfloat16_as_ushort(__float2bfloat16_rn(y));
    return a | (b << 16);
}
__device__ __forceinline__ void cvt_hilo(float x, float y, uint32_t& hi, uint32_t& lo) {
    hi = pack_bf2(x, y);
    float h0 = __int_as_float(hi << 16);
    float h1 = __int_as_float(hi & 0xffff0000u);
    lo = pack_bf2(x - h0, y - h1);
}

// MUFU-free tanh (FMA/ALU pipes only); |err| <= ~3.4e-5
__device__ __forceinline__ float tanh_fma(float x) {
    float t = fminf(fabsf(x), 5.5f) * 2.8853900817779268f;  // 2*log2(e)*|x|
    int n = __float2int_rn(t);
    float f = t - (float)n;
    float p = 1.5403530393381608e-4f;
    p = fmaf(p, f, 1.3333558146428443e-3f);
    p = fmaf(p, f, 9.6181291076284772e-3f);
    p = fmaf(p, f, 5.5504108664821580e-2f);
    p = fmaf(p, f, 2.4022650695910071e-1f);
    p = fmaf(p, f, 6.9314718055994531e-1f);
    p = fmaf(p, f, 1.0f);
    float E = __int_as_float(__float_as_int(p) + (n << 23)); // e^{2|x|}
    float D = E + 1.0f;
    float r = __int_as_float(0x7EF311C3 - __float_as_int(D));
    r = r * fmaf(-D, r, 2.0f);
    r = r * fmaf(-D, r, 2.0f);
    r = r * fmaf(-D, r, 2.0f);
    float y = fmaf(-2.0f, r, 1.0f);
    return copysignf(y, x);
}

__device__ __forceinline__ void ldsm4(uint32_t* r, uint32_t addr) {
    asm volatile("ldmatrix.sync.aligned.m8n8.x4.shared.b16 {%0,%1,%2,%3}, [%4];"
                 : "=r"(r[0]), "=r"(r[1]), "=r"(r[2]), "=r"(r[3]) : "r"(addr));
}
__device__ __forceinline__ void mma_bf16(float* c, const uint32_t* a, uint32_t b0, uint32_t b1) {
    asm volatile(
        "mma.sync.aligned.m16n8k16.row.col.f32.bf16.bf16.f32 "
        "{%0,%1,%2,%3}, {%4,%5,%6,%7}, {%8,%9}, {%0,%1,%2,%3};"
        : "+f"(c[0]), "+f"(c[1]), "+f"(c[2]), "+f"(c[3])
        : "r"(a[0]), "r"(a[1]), "r"(a[2]), "r"(a[3]), "r"(b0), "r"(b1));
}
#define CPA16(dst, src) \
    asm volatile("cp.async.cg.shared.global [%0], [%1], 16;" :: "r"(dst), "l"(src))

// ---------------------------------------------------------------------------
// conv (U only): fp32 -> tiled128 bf16 hi/lo, chunks of k=16.
// ---------------------------------------------------------------------------
__global__ void __launch_bounds__(128) conv_kernel(const float* __restrict__ S,
                                                   char* __restrict__ D) {
    const int blk = blockIdx.x;
    const int kc = blk & 15;
    const int r = threadIdx.x;

    const float* src = S + (size_t)((blk >> 4) * 128 + r) * HH + kc * 16;
    char* dst = D + (size_t)blk * UCHUNK;
    const uint32_t rowbase = (uint32_t)((r >> 3) * 2 * 128 + (r & 7) * 16);

#pragma unroll
    for (int q = 0; q < 4; q++) {
        float4 v = *(const float4*)(src + q * 4);
        uint2 ph, pl;
        cvt_hilo(v.x, v.y, ph.x, pl.x);
        cvt_hilo(v.z, v.w, ph.y, pl.y);
        uint32_t off = rowbase + (uint32_t)((q >> 1) * 128 + (q & 1) * 8);
        *(uint2*)(dst + off) = ph;
        *(uint2*)(dst + 4096 + off) = pl;
    }
}

// ---------------------------------------------------------------------------
// l[b,k] = sum_h W[k,h] * last_memory[b,h]
// ---------------------------------------------------------------------------
__global__ void __launch_bounds__(256) l_kernel(const float* __restrict__ lastm,
                                                const float* __restrict__ W) {
    __shared__ float lm[HH];
    __shared__ float Wt[32][HH + 1];
    const int b = blockIdx.x;
    const int tid = threadIdx.x;

    lm[tid] = lastm[b * HH + tid];
    __syncthreads();

    float acc = 0.0f;
    for (int h0 = 0; h0 < HH; h0 += 32) {
#pragma unroll
        for (int q = 0; q < 8; q++) {
            int f = tid + 256 * q;
            int k = f >> 3;
            int hq = f & 7;
            float4 v = *(const float4*)(W + k * HH + h0 + hq * 4);
            Wt[hq * 4 + 0][k] = v.x;
            Wt[hq * 4 + 1][k] = v.y;
            Wt[hq * 4 + 2][k] = v.z;
            Wt[hq * 4 + 3][k] = v.w;
        }
        __syncthreads();
#pragma unroll
        for (int hh = 0; hh < 32; hh++)
            acc = fmaf(Wt[hh][tid], lm[h0 + hh], acc);
        __syncthreads();
    }
    g_l[b * HH + tid] = acc;
}

// ---------------------------------------------------------------------------
// GEMM (fused conv-X, A-direct): CTA = 64 rows x 128 cols, 256 thr = 8 warps
// (2m x 4n), warp tile 32x32, 3 CTAs/SM. A fragments gathered per-thread as
// LDS.64 from the fp32 X ring (80B-padded rows: conflict-free 2-phase) and
// split hi/lo in registers -> no A smem ring, no LDSM-A, crossbar 40->32KB
// per CTA-chunk. B (U bf16 tiled128) ring x4 via cp.async + ldmatrix.
// Groups G_j = {B(j), X(j)}, prefetch distance 3, 1 sync per chunk.
// smem: [X 4x5120 @0][B 4x8KB @20480] = 52KB.
// ---------------------------------------------------------------------------
constexpr uint32_t XSLOT = 5120;       // 64 rows x 80B
constexpr uint32_t BOFF = 20480;
constexpr uint32_t GEMM_SMEM = 53248;  // 52KB -> 3 CTAs/SM

__global__ void __launch_bounds__(256, 3) gemm_kernel(const float* __restrict__ X,
                                                      const float* __restrict__ Vv) {
    extern __shared__ __align__(1024) char smem[];
    __shared__ float vsm[128];
    __shared__ float s_red[4][64];

    const uint32_t sb = smem_u32(smem);
    const int tid = threadIdx.x;
    const int lane = tid & 31;
    const int wid = tid >> 5;
    const int wm = wid & 1;       // 2 m-warps x 32 rows
    const int wn = wid >> 1;      // 4 n-warps x 32 cols
    const int m = blockIdx.x;     // 64-row tile
    const int nh = blockIdx.y;

    if (tid < 128) vsm[tid] = Vv[nh * 128 + tid];

    float acc[2][4][4];
#pragma unroll
    for (int i = 0; i < 2; i++)
#pragma unroll
        for (int j = 0; j < 4; j++)
#pragma unroll
            for (int k = 0; k < 4; k++) acc[i][j][k] = 0.0f;

    // X staging geometry: thread = (row = tid>>2, seg = tid&3)
    const int crow = tid >> 2;
    const int cseg = tid & 3;
    const uint32_t cxoff = (uint32_t)(crow * 80 + cseg * 16);
    const char* xbase = (const char*)(X + (size_t)m * 64 * HH)
                      + (size_t)crow * (HH * 4) + cseg * 16;

    // group G_j = { B(j) -> Bslot j%4 ; X(j) -> Xslot j%4 }
    auto stageG = [&](int j) {
        if (j < NCH) {
            const char* us = g_Uc + ((size_t)nh * NCH + j) * UCHUNK;
            uint32_t o = (uint32_t)tid * 32u;
            uint32_t d = sb + BOFF + (uint32_t)(j & 3) * 8192u + o;
            CPA16(d, us + o); CPA16(d + 16u, us + o + 16);
            CPA16(sb + (uint32_t)(j & 3) * XSLOT + cxoff, xbase + j * 64);
        }
        asm volatile("cp.async.commit_group;");
    };
    stageG(0); stageG(1); stageG(2);

    // A-direct lane addressing within the fp32 X slot (80B rows):
    // rows wm*32 + mt*16 + (lane>>2) + {0,8}; kpairs (lane&3) and (lane&3)+4
    const uint32_t arowb = (uint32_t)((wm * 32 + (lane >> 2)) * 80 + (lane & 3) * 8);

    // B ldmatrix lane addressing (tiled128)
    const uint32_t lb = (uint32_t)((lane & 7) * 16);
    const uint32_t ab1 = (uint32_t)((lane >> 3) & 1);
    const uint32_t ab2 = (uint32_t)(lane >> 4);

    for (int kc = 0; kc < NCH; kc++) {
        asm volatile("cp.async.wait_group 2;");   // G_kc complete
        __syncthreads();
        stageG(kc + 3);

        const uint32_t Xbase = sb + (uint32_t)(kc & 3) * XSLOT + arowb;
        const uint32_t Bbase = sb + BOFF + (uint32_t)(kc & 3) * 8192u;

        // A fragments: gather fp32 pairs, split hi/lo in registers
        uint32_t Ahi[2][4], Alo[2][4];
#pragma unroll
        for (int mt = 0; mt < 2; mt++) {
            const uint32_t rb = Xbase + (uint32_t)(mt * 16 * 80);
            float2 v00 = *(const float2*)(smem + (rb - sb));             // r,   kp
            float2 v10 = *(const float2*)(smem + (rb - sb) + 8 * 80);    // r+8, kp
            float2 v01 = *(const float2*)(smem + (rb - sb) + 32);        // r,   kp+4
            float2 v11 = *(const float2*)(smem + (rb - sb) + 8 * 80 + 32); // r+8, kp+4
            cvt_hilo(v00.x, v00.y, Ahi[mt][0], Alo[mt][0]);
            cvt_hilo(v10.x, v10.y, Ahi[mt][1], Alo[mt][1]);
            cvt_hilo(v01.x, v01.y, Ahi[mt][2], Alo[mt][2]);
            cvt_hilo(v11.x, v11.y, Ahi[mt][3], Alo[mt][3]);
        }

        uint32_t Bhi[2][4], Blo[2][4];
#pragma unroll
        for (int ntp = 0; ntp < 2; ntp++) {
            uint32_t tix = ((uint32_t)(wn * 4 + ntp * 2) + ab2) * 2 + ab1;
            uint32_t addr = Bbase + tix * 128u + lb;
            ldsm4(Bhi[ntp], addr);
            ldsm4(Blo[ntp], addr + 4096u);
        }

        // term-major: 8 independent MMAs per term (reuse distance 8)
#pragma unroll
        for (int mt = 0; mt < 2; mt++)
#pragma unroll
            for (int ntp = 0; ntp < 2; ntp++)
#pragma unroll
                for (int sub = 0; sub < 2; sub++)
                    mma_bf16(acc[mt][ntp * 2 + sub], Ahi[mt],
                             Bhi[ntp][sub * 2], Bhi[ntp][sub * 2 + 1]);
#pragma unroll
        for (int mt = 0; mt < 2; mt++)
#pragma unroll
            for (int ntp = 0; ntp < 2; ntp++)
#pragma unroll
                for (int sub = 0; sub < 2; sub++)
                    mma_bf16(acc[mt][ntp * 2 + sub], Ahi[mt],
                             Blo[ntp][sub * 2], Blo[ntp][sub * 2 + 1]);
#pragma unroll
        for (int mt = 0; mt < 2; mt++)
#pragma unroll
            for (int ntp = 0; ntp < 2; ntp++)
#pragma unroll
                for (int sub = 0; sub < 2; sub++)
                    mma_bf16(acc[mt][ntp * 2 + sub], Alo[mt],
                             Bhi[ntp][sub * 2], Bhi[ntp][sub * 2 + 1]);
    }

    // Epilogue: per row, sum over this warp's 32 cols of V[n]*tanh(acc+l)
#pragma unroll
    for (int mt = 0; mt < 2; mt++) {
#pragma unroll
        for (int rh = 0; rh < 2; rh++) {
            int rowl = wm * 32 + mt * 16 + rh * 8 + (lane >> 2);
            int rowg = m * 64 + rowl;
            const float* lr = g_l + (rowg / SS) * HH + nh * 128;
            float s = 0.0f;
#pragma unroll
            for (int nt = 0; nt < 4; nt++) {
#pragma unroll
                for (int cl = 0; cl < 2; cl++) {
                    int col = wn * 32 + nt * 8 + (lane & 3) * 2 + cl;
                    float v = acc[mt][nt][rh * 2 + cl] + __ldg(lr + col);
                    s = fmaf(vsm[col], tanh_fma(v), s);
                }
            }
            s += __shfl_xor_sync(0xffffffffu, s, 1);
            s += __shfl_xor_sync(0xffffffffu, s, 2);
            if ((lane & 3) == 0) s_red[wn][rowl] = s;
        }
    }
    __syncthreads();
    if (tid < 64)
        g_sc[nh * MROWS + m * 64 + tid] =
            (s_red[0][tid] + s_red[1][tid]) + (s_red[2][tid] + s_red[3][tid]);
}

// ---------------------------------------------------------------------------
// softmax over S + pooled (512 thr, S split in halves for 2x MLP) + projection
// ---------------------------------------------------------------------------
__global__ void __launch_bounds__(512) pool_kernel(const float* __restrict__ X,
                                                   const float* __restrict__ MW,
                                                   const float* __restrict__ Mb,
                                                   float* __restrict__ out) {
    __shared__ float sal[SS];
    __shared__ float red[16];
    __shared__ float4 red4[8];
    __shared__ float part[2][HH];

    const int b = blockIdx.x;
    const int tid = threadIdx.x;
    const int lane = tid & 31;
    const int w = tid >> 5;

    float v;
    if (tid < SS) {
        int idx = b * SS + tid;
        v = g_sc[idx] + g_sc[MROWS + idx];
    } else {
        v = __int_as_float(0xff800000);
    }
    float mx = v;
#pragma unroll
    for (int o = 16; o; o >>= 1) mx = fmaxf(mx, __shfl_xor_sync(0xffffffffu, mx, o));
    if (lane == 0) red[w] = mx;
    __syncthreads();
    float bm = red[0];
#pragma unroll
    for (int i = 1; i < 16; i++) bm = fmaxf(bm, red[i]);

    float e = (tid < SS) ? __expf(v - bm) : 0.0f;
    float s = e;
#pragma unroll
    for (int o = 16; o; o >>= 1) s += __shfl_xor_sync(0xffffffffu, s, o);
    __syncthreads();
    if (lane == 0) red[w] = s;
    __syncthreads();
    float bs = 0.0f;
#pragma unroll
    for (int i = 0; i < 16; i++) bs += red[i];

    if (tid < SS) sal[tid] = e / bs;
    __syncthreads();

    // pooling: thread = (half = tid>>8, h = tid&255), 100 rows per half
    {
        const int half = tid >> 8;
        const int h = tid & 255;
        const float* Xb = X + (size_t)b * SS * HH + h;
        const int s0 = half * 100;
        float acc = 0.0f;
#pragma unroll 10
        for (int sdx = s0; sdx < s0 + 100; sdx++)
            acc = fmaf(sal[sdx], Xb[(size_t)sdx * HH], acc);
        part[half][h] = acc;
    }
    __syncthreads();

    // projection: threads 0-255 (warps 0-7)
    if (tid < HH) {
        float acc = part[0][tid] + part[1][tid];
        float4 p;
        p.x = acc * MW[0 * HH + tid];
        p.y = acc * MW[1 * HH + tid];
        p.z = acc * MW[2 * HH + tid];
        p.w = acc * MW[3 * HH + tid];
#pragma unroll
        for (int o = 16; o; o >>= 1) {
            p.x += __shfl_xor_sync(0xffffffffu, p.x, o);
            p.y += __shfl_xor_sync(0xffffffffu, p.y, o);
            p.z += __shfl_xor_sync(0xffffffffu, p.z, o);
            p.w += __shfl_xor_sync(0xffffffffu, p.w, o);
        }
        if (lane == 0) red4[w] = p;
    }
    __syncthreads();
    if (tid == 0) {
        float4 t = red4[0];
#pragma unroll
        for (int i = 1; i < 8; i++) {
            t.x += red4[i].x; t.y += red4[i].y; t.z += red4[i].z; t.w += red4[i].w;
        }
        out[b * 4 + 0] = t.x + Mb[0];
        out[b * 4 + 1] = t.y + Mb[1];
        out[b * 4 + 2] = t.z + Mb[2];
        out[b * 4 + 3] = t.w + Mb[3];
    }
}

// ---------------------------------------------------------------------------
extern "C" void kernel_launch(void* const* d_in, const int* in_sizes, int n_in,
                              void* d_out, int out_size) {
    const float* X     = (const float*)d_in[0];
    const float* lastm = (const float*)d_in[1];
    const float* U     = (const float*)d_in[2];
    const float* W     = (const float*)d_in[3];
    const float* Vv    = (const float*)d_in[4];
    const float* MW    = (const float*)d_in[5];
    const float* Mb    = (const float*)d_in[6];
    float* out = (float*)d_out;

    char* uc;
    cudaGetSymbolAddress((void**)&uc, g_Uc);

    cudaFuncSetAttribute(gemm_kernel, cudaFuncAttributeMaxDynamicSharedMemorySize, GEMM_SMEM);

    conv_kernel<<<2 * NCH, 128>>>(U, uc);               // U -> tiled128 (k=16)
    l_kernel<<<BB, 256>>>(lastm, W);
    gemm_kernel<<<dim3(MT64, 2), 256, GEMM_SMEM>>>(X, Vv);
    pool_kernel<<<BB, 512>>>(X, MW, Mb, out);
}